// round 15
// baseline (speedup 1.0000x reference)
#include <cuda_runtime.h>
#include <cuda_bf16.h>
#include <math.h>

#define TT 64
#define BATCH 32
#define PE 128
#define WE 512
#define PH 256
#define WH 1024
#define PV 48
#define WV 32000
#define GRID 148
#define TPB 512
#define SLDA 1032
#define SLDA2 264

// ---------------- fp32 scratch ----------------
#define OFF_GPSEQ 0
#define OFF_GWSEQ (OFF_GPSEQ + TT*BATCH*4*PH)
#define OFF_PC    (OFF_GWSEQ + TT*BATCH*4*WH)
#define OFF_WC0   (OFF_PC + BATCH*PH)
#define OFF_WC1   (OFF_WC0 + BATCH*WH)
#define OFF_WG0H  (OFF_WC1 + BATCH*WH)
#define OFF_WG1H  (OFF_WG0H + BATCH*4*WH)
#define OFF_PHSEQ (OFF_WG1H + BATCH*4*WH)
#define SCRATCH_TOTAL (OFF_PHSEQ + TT*BATCH*PH)

__device__ float g_scratch[SCRATCH_TOTAL];
__device__ unsigned g_flags[GRID];
__device__ unsigned g_gen;

// persist weights in PACKED fragment order: [N/16][K/16][32][4 bf16x2 words]
__device__ __nv_bfloat16 g_bw2p  [1024*1024];
__device__ __nv_bfloat16 g_bwhh1 [4096*1024];
__device__ __nv_bfloat16 g_bwhh0 [4096*1024];
__device__ __nv_bfloat16 g_bpih  [1024*1024];
__device__ __nv_bfloat16 g_bphh  [1024*256];
__device__ __nv_bfloat16 g_bp2w  [256*256];
__device__ __nv_bfloat16 g_bwih0p[4096*256];
__device__ __nv_bfloat16 g_bwih1 [4096*1024];
// plain [N,K] bf16 for mma_gemm
__device__ __nv_bfloat16 g_bpihe [1024*128];
__device__ __nv_bfloat16 g_bwih0e[4096*512];
__device__ __nv_bfloat16 g_bproj1[512*1024];
// states / activations
__device__ __nv_bfloat16 g_bwh1  [32*1024];
__device__ __nv_bfloat16 g_bwh0  [32*1024];
__device__ __nv_bfloat16 g_bph   [2][32*256];
__device__ __nv_bfloat16 g_blastw[32*1024];
__device__ __nv_bfloat16 g_pembin[TT*BATCH*PE];
__device__ __nv_bfloat16 g_wembin[TT*BATCH*WE];
__device__ __nv_bfloat16 g_whseq_bf[(size_t)TT*BATCH*WH];
__device__ __nv_bfloat16 g_wemb_bf[(size_t)WV*WE];
__device__ __nv_bfloat16 g_he_bf[(size_t)TT*BATCH*WE];

#define SMEM_A1  0
#define SMEM_A2  66048
#define SMEM_RED 132096
#define SMEM_DYN 166912

__device__ __forceinline__ float sigf(float x) { return 1.f/(1.f+expf(-x)); }

__device__ __forceinline__ void mma16816(float* c, const unsigned* a, const unsigned* b)
{
    asm volatile("mma.sync.aligned.m16n8k16.row.col.f32.bf16.bf16.f32 "
        "{%0,%1,%2,%3}, {%4,%5,%6,%7}, {%8,%9}, {%0,%1,%2,%3};"
        : "+f"(c[0]), "+f"(c[1]), "+f"(c[2]), "+f"(c[3])
        : "r"(a[0]), "r"(a[1]), "r"(a[2]), "r"(a[3]), "r"(b[0]), "r"(b[1]));
}
__device__ __forceinline__ void ldsm4(unsigned* r, const void* p)
{
    unsigned ad = (unsigned)__cvta_generic_to_shared(p);
    asm volatile("ldmatrix.sync.aligned.m8n8.x4.shared.b16 {%0,%1,%2,%3}, [%4];"
        : "=r"(r[0]), "=r"(r[1]), "=r"(r[2]), "=r"(r[3]) : "r"(ad));
}
__device__ __forceinline__ unsigned ld_acq(const unsigned* p)
{
    unsigned v;
    asm volatile("ld.acquire.gpu.u32 %0, [%1];" : "=r"(v) : "l"(p) : "memory");
    return v;
}
__device__ __forceinline__ void st_rel(unsigned* p, unsigned v)
{
    asm volatile("st.release.gpu.u32 [%0], %1;" :: "l"(p), "r"(v) : "memory");
}

// ---------------- init ----------------
__global__ void init_kernel(const int* __restrict__ pos, const int* __restrict__ word,
                            const float* __restrict__ pos_emb, const float* __restrict__ word_emb,
                            float* __restrict__ S)
{
    int i = blockIdx.x*blockDim.x + threadIdx.x;
    int st = gridDim.x*blockDim.x;
    for (int x = i; x < TT*BATCH*PE; x += st) {
        int tb = x/PE;
        g_pembin[x] = __float2bfloat16(pos_emb[pos[tb]*PE + x - tb*PE]);
    }
    for (int x = i; x < TT*BATCH*WE; x += st) {
        int tb = x/WE;
        g_wembin[x] = __float2bfloat16(word_emb[word[tb]*WE + x - tb*WE]);
    }
    for (int x = i; x < BATCH*PH; x += st) S[OFF_PC + x] = 0.f;
    for (int x = i; x < 2*BATCH*WH; x += st) S[OFF_WC0 + x] = 0.f;
    unsigned* z1 = (unsigned*)g_bwh1; unsigned* z2 = (unsigned*)g_bwh0; unsigned* z3 = (unsigned*)g_bph;
    for (int x = i; x < 16384; x += st) { z1[x] = 0u; z2[x] = 0u; }
    for (int x = i; x < 8192; x += st) z3[x] = 0u;
    if (i < GRID) g_flags[i] = 0u;
    if (i == 0) g_gen = 0u;
}

// ---------------- conversions ----------------
__global__ void conv_bf16(const float* __restrict__ src, __nv_bfloat16* __restrict__ dst, int n4)
{
    int i = blockIdx.x*blockDim.x + threadIdx.x;
    int st = gridDim.x*blockDim.x;
    const float4* s4 = (const float4*)src;
    for (; i < n4; i += st) {
        float4 v = s4[i];
        *(__nv_bfloat162*)(dst + (size_t)i*4)   = __floats2bfloat162_rn(v.x, v.y);
        *(__nv_bfloat162*)(dst + (size_t)i*4+2) = __floats2bfloat162_rn(v.z, v.w);
    }
}
__device__ __forceinline__ void conv_seg(const float* __restrict__ src, __nv_bfloat16* __restrict__ dst,
                                         int rows, int src_ld, int col0, int cols)
{
    int half = cols >> 1;
    long tot = (long)rows*half;
    long idx = (long)blockIdx.x*blockDim.x + threadIdx.x;
    long st  = (long)gridDim.x*blockDim.x;
    for (long i = idx; i < tot; i += st) {
        int r = (int)(i/half), c = (int)(i - (long)r*half)*2;
        float2 v = *(const float2*)&src[(size_t)r*src_ld + col0 + c];
        *(__nv_bfloat162*)&dst[(size_t)r*cols + c] = __floats2bfloat162_rn(v.x, v.y);
    }
}
// pack W[N, col0:col0+K] into fragment order
__device__ __forceinline__ void pack_seg(const float* __restrict__ src, __nv_bfloat16* __restrict__ dst,
                                         int N, int src_ld, int col0, int K)
{
    int NT = N >> 4, KT = K >> 4;
    long tot = (long)NT*KT*32;
    long idx = (long)blockIdx.x*blockDim.x + threadIdx.x;
    long st  = (long)gridDim.x*blockDim.x;
    for (long i = idx; i < tot; i += st) {
        int lane = (int)(i & 31);
        long tk = i >> 5;
        int kt = (int)(tk % KT);
        int nt = (int)(tk / KT);
        int r0 = nt*16 + (lane>>2);
        int c0 = col0 + kt*16 + 2*(lane&3);
        float2 w0 = *(const float2*)&src[(size_t)r0*src_ld + c0];
        float2 w1 = *(const float2*)&src[(size_t)r0*src_ld + c0 + 8];
        float2 w2 = *(const float2*)&src[(size_t)(r0+8)*src_ld + c0];
        float2 w3 = *(const float2*)&src[(size_t)(r0+8)*src_ld + c0 + 8];
        __nv_bfloat162* d = (__nv_bfloat162*)(dst + i*8);
        d[0] = __floats2bfloat162_rn(w0.x, w0.y);
        d[1] = __floats2bfloat162_rn(w1.x, w1.y);
        d[2] = __floats2bfloat162_rn(w2.x, w2.y);
        d[3] = __floats2bfloat162_rn(w3.x, w3.y);
    }
}
__global__ void conv_all(const float* w2p_W, const float* w_Whh1, const float* w_Whh0,
                         const float* p_Wih0, const float* p_Whh0, const float* p2w_W,
                         const float* w_Wih0, const float* w_Wih1, const float* word_proj1_W)
{
    pack_seg(w2p_W,   g_bw2p,   1024, 1024, 0,   1024);
    pack_seg(w_Whh1,  g_bwhh1,  4096, 1024, 0,   1024);
    pack_seg(w_Whh0,  g_bwhh0,  4096, 1024, 0,   1024);
    pack_seg(p_Wih0,  g_bpih,   1024, 1152, 128, 1024);
    pack_seg(p_Whh0,  g_bphh,   1024, 256,  0,   256);
    pack_seg(p2w_W,   g_bp2w,   256,  256,  0,   256);
    pack_seg(w_Wih0,  g_bwih0p, 4096, 768,  512, 256);
    pack_seg(w_Wih1,  g_bwih1,  4096, 1024, 0,   1024);
    conv_seg(p_Wih0,       g_bpihe,  1024, 1152, 0,   128);
    conv_seg(w_Wih0,       g_bwih0e, 4096, 768,  0,   512);
    conv_seg(word_proj1_W, g_bproj1, 512,  1024, 0,   1024);
}

// ---------------- two-hop acquire/release grid barrier (R13) ----------------
__device__ __forceinline__ void grid_bar(unsigned epoch)
{
    __syncthreads();
    if (threadIdx.x == 0) st_rel(&g_flags[blockIdx.x], epoch);
    if (blockIdx.x == 0) {
        if (threadIdx.x < GRID)
            while (ld_acq(&g_flags[threadIdx.x]) < epoch) { }
        __syncthreads();
        if (threadIdx.x == 0) st_rel(&g_gen, epoch);
    }
    if (threadIdx.x == 0)
        while (ld_acq(&g_gen) < epoch) { }
    __syncthreads();
}

// ---------------- persist building blocks ----------------
__device__ __forceinline__ void stage_A(const __nv_bfloat16* __restrict__ A, int K, int ald,
                                        __nv_bfloat16* __restrict__ sd)
{
    int Kc = K >> 3;
    for (int i = threadIdx.x; i < 32*Kc; i += TPB) {
        int row = i/Kc, c = i - row*Kc;
        uint4 v = __ldcg((const uint4*)&A[row*K + (c<<3)]);
        *(uint4*)&sd[row*ald + (c<<3)] = v;
    }
}
__device__ __forceinline__ void gen_accum_p(const __nv_bfloat16* __restrict__ sAp, int ald,
    const __nv_bfloat16* __restrict__ Wp, int KT, int nt, int kb, int ke,
    float* acc, int lane)
{
    const __nv_bfloat16* ar = sAp + (lane&15)*ald + 8*(lane>>4);
    const uint4* wp = (const uint4*)Wp + ((size_t)nt*KT)*32 + lane;
    #pragma unroll 4
    for (int kk = kb; kk < ke; kk++) {
        unsigned a0[4], a1[4];
        uint4 w = __ldg(wp + (size_t)kk*32);
        ldsm4(a0, ar + kk*16);
        ldsm4(a1, ar + 16*ald + kk*16);
        unsigned b0[2] = {w.x, w.y}, b1[2] = {w.z, w.w};
        mma16816(acc+0, a0, b0);  mma16816(acc+8, a1, b0);
        mma16816(acc+4, a0, b1);  mma16816(acc+12, a1, b1);
    }
}
__device__ __forceinline__ void red_store(float* red, int wrp, int lane, const float* acc)
{
    float* p = red + (wrp*32 + lane)*17;
    #pragma unroll
    for (int i = 0; i < 16; i++) p[i] = acc[i];
}
__device__ __forceinline__ float red_gather(const float* red, int ts, int li, int ai)
{
    const float* p = red + (ts*4*32 + li)*17 + ai;
    return p[0] + p[32*17] + p[2*32*17] + p[3*32*17];
}
__device__ __forceinline__ void elem_map(int b, int jl, int& li, int& ai)
{
    li = (b&7)*4 + ((jl&7)>>1);
    ai = (b>>4)*8 + (jl>>3)*4 + ((b>>3)&1)*2 + (jl&1);
}

// ---------------- persistent tensor-core sequential phase ----------------
__global__ __launch_bounds__(TPB, 1) void persist_kernel(
    const float* __restrict__ w2p_b, const float* __restrict__ p2w_b,
    const float* __restrict__ w_bih1, const float* __restrict__ w_bhh1,
    float* __restrict__ S)
{
    extern __shared__ char smem[];
    __nv_bfloat16* sA1 = (__nv_bfloat16*)(smem + SMEM_A1);
    __nv_bfloat16* sA2 = (__nv_bfloat16*)(smem + SMEM_A2);
    float* red = (float*)(smem + SMEM_RED);

    float* gpseq = S + OFF_GPSEQ;
    float* gwseq = S + OFF_GWSEQ;
    float* pc    = S + OFF_PC;
    float* wc0   = S + OFF_WC0;
    float* wc1   = S + OFF_WC1;
    float* wg0h  = S + OFF_WG0H;
    float* wg1h  = S + OFF_WG1H;
    float* phseq = S + OFF_PHSEQ;

    int lane = threadIdx.x & 31;
    int wrp  = threadIdx.x >> 5;
    int ts   = wrp >> 2;
    int ks   = wrp & 3;
    int eb   = threadIdx.x >> 4;
    int ej   = threadIdx.x & 15;
    int eli, eai;
    elem_map(eb, ej, eli, eai);
    int pp = 0;
    unsigned epoch = 0;

    for (int t = 0; t < TT; t++) {
        // ===== A: lastw (blocks 0-15) || wg1h/wg0h bulk (blocks 16-143) =====
        // both depend only on wh1/wh0 from step t-1 (barrier'd at end of prev step)
        if (blockIdx.x < 16) {
            stage_A(g_bwh1, 1024, SLDA, sA1);
            __syncthreads();
            int nt = blockIdx.x*4 + ts;
            float acc[16];
            #pragma unroll
            for (int i = 0; i < 16; i++) acc[i] = 0.f;
            gen_accum_p(sA1, SLDA, g_bw2p, 64, nt, ks*16, ks*16+16, acc, lane);
            red_store(red, wrp, lane, acc);
            __syncthreads();
            #pragma unroll
            for (int tt2 = 0; tt2 < 4; tt2++) {
                int n = (blockIdx.x*4 + tt2)*16 + ej;
                float v = red_gather(red, tt2, eli, eai);
                g_blastw[eb*1024 + n] = __float2bfloat16(tanhf(v + w2p_b[n]));
            }
        } else {
            int base = (blockIdx.x - 16)*4;
            if (base < 512) {
                const __nv_bfloat16* sAu;
                if (base < 256) { stage_A(g_bwh1, 1024, SLDA, sA1); sAu = sA1; }
                else            { stage_A(g_bwh0, 1024, SLDA, sA2); sAu = sA2; }
                __syncthreads();
                int wt = base + ts;
                const __nv_bfloat16* Wp = (wt < 256) ? g_bwhh1 : g_bwhh0;
                int nt = (wt < 256) ? wt : wt - 256;
                float acc[16];
                #pragma unroll
                for (int i = 0; i < 16; i++) acc[i] = 0.f;
                gen_accum_p(sAu, SLDA, Wp, 64, nt, ks*16, ks*16+16, acc, lane);
                red_store(red, wrp, lane, acc);
                __syncthreads();
                #pragma unroll
                for (int tt2 = 0; tt2 < 4; tt2++) {
                    int wt2 = base + tt2;
                    float v = red_gather(red, tt2, eli, eai);
                    if (wt2 < 256) wg1h[eb*4096 + wt2*16 + ej] = v;
                    else           wg0h[eb*4096 + (wt2-256)*16 + ej] = v;
                }
            }
        }
        grid_bar(++epoch);

        // ===== B: POS gates + cell (16 blocks) =====
        if (blockIdx.x < 16) {
            stage_A(g_blastw, 1024, SLDA, sA1);
            stage_A(g_bph[pp], 256, SLDA2, sA2);
            __syncthreads();
            int j0 = blockIdx.x*16;
            int nt = ts*16 + blockIdx.x;
            float acc[16];
            #pragma unroll
            for (int i = 0; i < 16; i++) acc[i] = 0.f;
            int sb = ks*20, se = sb + 20;
            if (sb < 64) gen_accum_p(sA1, SLDA, g_bpih, 64, nt, sb, se < 64 ? se : 64, acc, lane);
            if (se > 64) gen_accum_p(sA2, SLDA2, g_bphh, 16, nt, sb > 64 ? sb-64 : 0, se-64, acc, lane);
            red_store(red, wrp, lane, acc);
            __syncthreads();
            {
                int j = j0 + ej;
                const float* pre = gpseq + ((size_t)t*BATCH + eb)*(4*PH) + j;
                float gi = red_gather(red, 0, eli, eai) + pre[0*PH];
                float gf = red_gather(red, 1, eli, eai) + pre[1*PH];
                float gg = red_gather(red, 2, eli, eai) + pre[2*PH];
                float go = red_gather(red, 3, eli, eai) + pre[3*PH];
                int idx = eb*PH + j;
                float cn = sigf(gf)*pc[idx] + sigf(gi)*tanhf(gg);
                float hn = sigf(go)*tanhf(cn);
                pc[idx] = cn;
                g_bph[pp^1][idx] = __float2bfloat16(hn);
                phseq[((size_t)t*BATCH + eb)*PH + j] = hn;
            }
        }
        grid_bar(++epoch);

        // ===== S4: lastp prologue + WORD L0 gates + cell — 64 blocks =====
        if (blockIdx.x < 64) {
            stage_A(g_bph[pp^1], 256, SLDA2, sA2);
            __syncthreads();
            {
                float pacc[16];
                #pragma unroll
                for (int i = 0; i < 16; i++) pacc[i] = 0.f;
                gen_accum_p(sA2, SLDA2, g_bp2w, 16, wrp, 0, 16, pacc, lane);
                int n0 = wrp*16;
                #pragma unroll
                for (int mf = 0; mf < 2; mf++)
                #pragma unroll
                for (int f = 0; f < 2; f++) {
                    int rb = mf*16 + (lane>>2);
                    int cl = n0 + f*8 + 2*(lane&3);
                    float b0 = p2w_b[cl], b1 = p2w_b[cl+1];
                    const float* a = pacc + mf*8 + f*4;
                    *(__nv_bfloat162*)&sA1[rb*SLDA + cl] =
                        __floats2bfloat162_rn(tanhf(a[0]+b0), tanhf(a[1]+b1));
                    *(__nv_bfloat162*)&sA1[(rb+8)*SLDA + cl] =
                        __floats2bfloat162_rn(tanhf(a[2]+b0), tanhf(a[3]+b1));
                }
            }
            __syncthreads();
            int j0 = blockIdx.x*16;
            int nt = ts*64 + blockIdx.x;
            float acc[16];
            #pragma unroll
            for (int i = 0; i < 16; i++) acc[i] = 0.f;
            gen_accum_p(sA1, SLDA, g_bwih0p, 16, nt, ks*4, ks*4+4, acc, lane);
            red_store(red, wrp, lane, acc);
            __syncthreads();
            {
                int j = j0 + ej;
                const float* pre = gwseq + ((size_t)t*BATCH + eb)*(4*WH) + j;
                const float* hid = wg0h + (size_t)eb*4096 + j;
                float gi = red_gather(red, 0, eli, eai) + pre[0*WH] + __ldcg(hid + 0*WH);
                float gf = red_gather(red, 1, eli, eai) + pre[1*WH] + __ldcg(hid + 1*WH);
                float gg = red_gather(red, 2, eli, eai) + pre[2*WH] + __ldcg(hid + 2*WH);
                float go = red_gather(red, 3, eli, eai) + pre[3*WH] + __ldcg(hid + 3*WH);
                int idx = eb*WH + j;
                float cn = sigf(gf)*wc0[idx] + sigf(gi)*tanhf(gg);
                float hn = sigf(go)*tanhf(cn);
                wc0[idx] = cn;
                g_bwh0[idx] = __float2bfloat16(hn);
            }
        }
        grid_bar(++epoch);

        // ===== S5: WORD L1 gates + cell — 64 blocks, K=1024 =====
        if (blockIdx.x < 64) {
            stage_A(g_bwh0, 1024, SLDA, sA1);
            __syncthreads();
            int j0 = blockIdx.x*16;
            int nt = ts*64 + blockIdx.x;
            float acc[16];
            #pragma unroll
            for (int i = 0; i < 16; i++) acc[i] = 0.f;
            gen_accum_p(sA1, SLDA, g_bwih1, 64, nt, ks*16, ks*16+16, acc, lane);
            red_store(red, wrp, lane, acc);
            __syncthreads();
            {
                int j = j0 + ej;
                const float* hid = wg1h + (size_t)eb*4096 + j;
                float gi = red_gather(red, 0, eli, eai) + __ldcg(hid + 0*WH) + w_bih1[0*WH+j] + w_bhh1[0*WH+j];
                float gf = red_gather(red, 1, eli, eai) + __ldcg(hid + 1*WH) + w_bih1[1*WH+j] + w_bhh1[1*WH+j];
                float gg = red_gather(red, 2, eli, eai) + __ldcg(hid + 2*WH) + w_bih1[2*WH+j] + w_bhh1[2*WH+j];
                float go = red_gather(red, 3, eli, eai) + __ldcg(hid + 3*WH) + w_bih1[3*WH+j] + w_bhh1[3*WH+j];
                int idx = eb*WH + j;
                float cn = sigf(gf)*wc1[idx] + sigf(gi)*tanhf(gg);
                float hn = sigf(go)*tanhf(cn);
                wc1[idx] = cn;
                g_bwh1[idx] = __float2bfloat16(hn);
                g_whseq_bf[((size_t)t*BATCH + eb)*WH + j] = __float2bfloat16(hn);
            }
        }
        grid_bar(++epoch);
        pp ^= 1;
    }
}

// ---------------- generic bf16 mma GEMM (R13 single-buffered) ----------------
template<int OUT_BF>
__global__ __launch_bounds__(256) void mma_gemm(const __nv_bfloat16* __restrict__ Abf,
                                                const __nv_bfloat16* __restrict__ Bbf,
                                                const float* __restrict__ bias1,
                                                const float* __restrict__ bias2,
                                                void* __restrict__ Cv, int N, int K)
{
    __shared__ __nv_bfloat16 sAm[128][40];
    __shared__ __nv_bfloat16 sBm[128][40];
    int tid = threadIdx.x, lane = tid&31, wid = tid>>5;
    int wm = wid>>2, wn = wid&3;
    int bm = blockIdx.y*128, bn = blockIdx.x*128;
    float acc[4][4][4] = {};
    for (int kt = 0; kt < K; kt += 32) {
        __syncthreads();
        #pragma unroll
        for (int c = 0; c < 2; c++) {
            int ch = tid + c*256;
            int row = ch>>2, seg = (ch&3)*8;
            *(uint4*)&sAm[row][seg] = *(const uint4*)&Abf[(size_t)(bm+row)*K + kt + seg];
            *(uint4*)&sBm[row][seg] = *(const uint4*)&Bbf[(size_t)(bn+row)*K + kt + seg];
        }
        __syncthreads();
        #pragma unroll
        for (int k16 = 0; k16 < 2; k16++) {
            unsigned afrag[4][4], bfrag[4][2];
            #pragma unroll
            for (int mf = 0; mf < 4; mf++)
                ldsm4(afrag[mf], &sAm[wm*64 + mf*16 + (lane&15)][k16*16 + (lane>>4)*8]);
            #pragma unroll
            for (int np = 0; np < 2; np++) {
                unsigned r[4];
                ldsm4(r, &sBm[wn*32 + np*16 + (lane&7) + ((lane>>4)<<3)][k16*16 + (((lane>>3)&1)<<3)]);
                bfrag[np*2][0] = r[0]; bfrag[np*2][1] = r[1];
                bfrag[np*2+1][0] = r[2]; bfrag[np*2+1][1] = r[3];
            }
            #pragma unroll
            for (int mf = 0; mf < 4; mf++)
                #pragma unroll
                for (int nf = 0; nf < 4; nf++)
                    mma16816(acc[mf][nf], afrag[mf], bfrag[nf]);
        }
    }
    int tg = lane>>2, tc = (lane&3)*2;
    #pragma unroll
    for (int nf = 0; nf < 4; nf++) {
        int n = bn + wn*32 + nf*8 + tc;
        float b0 = (bias1 ? bias1[n]   : 0.f) + (bias2 ? bias2[n]   : 0.f);
        float b1 = (bias1 ? bias1[n+1] : 0.f) + (bias2 ? bias2[n+1] : 0.f);
        #pragma unroll
        for (int mf = 0; mf < 4; mf++) {
            int m0 = bm + wm*64 + mf*16 + tg;
            float v00 = acc[mf][nf][0]+b0, v01 = acc[mf][nf][1]+b1;
            float v10 = acc[mf][nf][2]+b0, v11 = acc[mf][nf][3]+b1;
            if (OUT_BF) {
                __nv_bfloat16* C = (__nv_bfloat16*)Cv;
                *(__nv_bfloat162*)&C[(size_t)m0*N + n]     = __floats2bfloat162_rn(v00, v01);
                *(__nv_bfloat162*)&C[(size_t)(m0+8)*N + n] = __floats2bfloat162_rn(v10, v11);
            } else {
                float* C = (float*)Cv;
                *(float2*)&C[(size_t)m0*N + n]     = make_float2(v00, v01);
                *(float2*)&C[(size_t)(m0+8)*N + n] = make_float2(v10, v11);
            }
        }
    }
}

// ---------------- pos projection + log_softmax ----------------
__global__ void pos_out_kernel(const float* __restrict__ phseq, const float* __restrict__ proj_W,
                               const float* __restrict__ proj_b, float* __restrict__ out)
{
    int row = blockIdx.x;
    const float* h = phseq + row*PH;
    __shared__ float sh[PH];
    __shared__ float logits[PV];
    __shared__ float lse;
    for (int i = threadIdx.x; i < PH; i += 64) sh[i] = h[i];
    __syncthreads();
    if (threadIdx.x < PV) {
        float s = proj_b[threadIdx.x];
        const float* wr = proj_W + threadIdx.x*PH;
        #pragma unroll 4
        for (int k = 0; k < PH; k++) s += sh[k]*wr[k];
        logits[threadIdx.x] = s;
    }
    __syncthreads();
    if (threadIdx.x == 0) {
        float m = -1e30f;
        for (int i = 0; i < PV; i++) m = fmaxf(m, logits[i]);
        float ssum = 0.f;
        for (int i = 0; i < PV; i++) ssum += expf(logits[i]-m);
        lse = m + logf(ssum);
    }
    __syncthreads();
    if (threadIdx.x < PV) out[row*PV + threadIdx.x] = logits[threadIdx.x] - lse;
}

// ---------------- in-place log_softmax (word) ----------------
__global__ void word_lsm(float* __restrict__ out)
{
    int row = blockIdx.x;
    float* r = out + (long)row*WV;
    float m = -1e30f, s = 0.f;
    for (int i = threadIdx.x; i < WV; i += blockDim.x) {
        float v = r[i];
        if (v > m) { s = s*expf(m-v) + 1.f; m = v; } else s += expf(v-m);
    }
    __shared__ float sm[256], ss[256];
    sm[threadIdx.x] = m; ss[threadIdx.x] = s;
    __syncthreads();
    for (int off = 128; off > 0; off >>= 1) {
        if (threadIdx.x < off) {
            float m1 = sm[threadIdx.x], s1 = ss[threadIdx.x];
            float m2 = sm[threadIdx.x+off], s2 = ss[threadIdx.x+off];
            float mm = fmaxf(m1, m2);
            sm[threadIdx.x] = mm;
            ss[threadIdx.x] = s1*expf(m1-mm) + s2*expf(m2-mm);
        }
        __syncthreads();
    }
    float lse = sm[0] + logf(ss[0]);
    for (int i = threadIdx.x; i < WV; i += blockDim.x) r[i] -= lse;
}

// ---------------- host ----------------
extern "C" void kernel_launch(void* const* d_in, const int* in_sizes, int n_in,
                              void* d_out, int out_size)
{
    (void)in_sizes; (void)n_in; (void)out_size;
    const int*   pos          = (const int*)  d_in[0];
    const int*   word         = (const int*)  d_in[1];
    const float* pos_emb_W    = (const float*)d_in[2];
    const float* word_emb_W   = (const float*)d_in[3];
    const float* w2p_W        = (const float*)d_in[4];
    const float* w2p_b        = (const float*)d_in[5];
    const float* p2w_W        = (const float*)d_in[6];
    const float* p2w_b        = (const float*)d_in[7];
    const float* p_Wih0       = (const float*)d_in[8];
    const float* p_Whh0       = (const float*)d_in[9];
    const float* p_bih0       = (const float*)d_in[10];
    const float* p_bhh0       = (const float*)d_in[11];
    const float* w_Wih0       = (const float*)d_in[12];
    const float* w_Whh0       = (const float*)d_in[13];
    const float* w_bih0       = (const float*)d_in[14];
    const float* w_bhh0       = (const float*)d_in[15];
    const float* w_Wih1       = (const float*)d_in[16];
    const float* w_Whh1       = (const float*)d_in[17];
    const float* w_bih1       = (const float*)d_in[18];
    const float* w_bhh1       = (const float*)d_in[19];
    const float* pos_proj_W   = (const float*)d_in[20];
    const float* pos_proj_b   = (const float*)d_in[21];
    const float* word_proj1_W = (const float*)d_in[22];
    const float* word_proj1_b = (const float*)d_in[23];
    const float* word_proj2_b = (const float*)d_in[24];
    float* out = (float*)d_out;

    float* S; cudaGetSymbolAddress((void**)&S, g_scratch);
    __nv_bfloat16 *wemb_bf, *he_bf, *pembin, *wembin, *whseq_bf, *bpihe, *bwih0e, *bproj1;
    cudaGetSymbolAddress((void**)&wemb_bf, g_wemb_bf);
    cudaGetSymbolAddress((void**)&he_bf, g_he_bf);
    cudaGetSymbolAddress((void**)&pembin, g_pembin);
    cudaGetSymbolAddress((void**)&wembin, g_wembin);
    cudaGetSymbolAddress((void**)&whseq_bf, g_whseq_bf);
    cudaGetSymbolAddress((void**)&bpihe, g_bpihe);
    cudaGetSymbolAddress((void**)&bwih0e, g_bwih0e);
    cudaGetSymbolAddress((void**)&bproj1, g_bproj1);

    float* gpseq = S + OFF_GPSEQ;
    float* gwseq = S + OFF_GWSEQ;
    float* phseq = S + OFF_PHSEQ;

    static bool attr_set = false;
    if (!attr_set) {
        cudaFuncSetAttribute(persist_kernel, cudaFuncAttributeMaxDynamicSharedMemorySize, SMEM_DYN);
        attr_set = true;
    }

    init_kernel<<<512, 256>>>(pos, word, pos_emb_W, word_emb_W, S);
    conv_bf16<<<2048, 256>>>(word_emb_W, wemb_bf, (int)((size_t)WV*WE/4));
    conv_all<<<592, 256>>>(w2p_W, w_Whh1, w_Whh0, p_Wih0, p_Whh0, p2w_W,
                           w_Wih0, w_Wih1, word_proj1_W);

    mma_gemm<0><<<dim3(4*PH/128, TT*BATCH/128), 256>>>(pembin, bpihe, p_bih0, p_bhh0,
                                                       gpseq, 4*PH, PE);
    mma_gemm<0><<<dim3(4*WH/128, TT*BATCH/128), 256>>>(wembin, bwih0e, w_bih0, w_bhh0,
                                                       gwseq, 4*WH, WE);

    persist_kernel<<<GRID, TPB, SMEM_DYN>>>(w2p_b, p2w_b, w_bih1, w_bhh1, S);

    pos_out_kernel<<<TT*BATCH, 64>>>(phseq, pos_proj_W, pos_proj_b, out);

    mma_gemm<1><<<dim3(WE/128, TT*BATCH/128), 256>>>(whseq_bf, bproj1, word_proj1_b, nullptr,
                                                     he_bf, WE, WH);
    float* wout = out + (long)TT*BATCH*PV;
    mma_gemm<0><<<dim3(WV/128, TT*BATCH/128), 256>>>(he_bf, wemb_bf, word_proj2_b, nullptr,
                                                     wout, WV, WE);
    word_lsm<<<TT*BATCH, 256>>>(wout);
}

// round 16
// speedup vs baseline: 1.4131x; 1.4131x over previous
#include <cuda_runtime.h>
#include <cuda_bf16.h>
#include <math.h>

#define TT 64
#define BATCH 32
#define PE 128
#define WE 512
#define PH 256
#define WH 1024
#define PV 48
#define WV 32000
#define GRID 148
#define TPB 512
#define SLDA 1032
#define SLDA2 264

// ---------------- fp32 scratch ----------------
#define OFF_GPSEQ 0
#define OFF_GWSEQ (OFF_GPSEQ + TT*BATCH*4*PH)
#define OFF_PC    (OFF_GWSEQ + TT*BATCH*4*WH)
#define OFF_WC0   (OFF_PC + BATCH*PH)
#define OFF_WC1   (OFF_WC0 + BATCH*WH)
#define OFF_WG0H  (OFF_WC1 + BATCH*WH)
#define OFF_WG1H  (OFF_WG0H + BATCH*4*WH)
#define OFF_PHSEQ (OFF_WG1H + BATCH*4*WH)
#define SCRATCH_TOTAL (OFF_PHSEQ + TT*BATCH*PH)

__device__ float g_scratch[SCRATCH_TOTAL];
__device__ unsigned g_flags[GRID];
__device__ unsigned g_gen;

// persist weights in PACKED fragment order: [N/16][K/16][32][4 bf16x2 words]
__device__ __nv_bfloat16 g_bw2p  [1024*1024];
__device__ __nv_bfloat16 g_bwhh1 [4096*1024];
__device__ __nv_bfloat16 g_bwhh0 [4096*1024];
__device__ __nv_bfloat16 g_bpih  [1024*1024];
__device__ __nv_bfloat16 g_bphh  [1024*256];
__device__ __nv_bfloat16 g_bp2w  [256*256];
__device__ __nv_bfloat16 g_bwih0p[4096*256];
__device__ __nv_bfloat16 g_bwih1 [4096*1024];
// plain [N,K] bf16 for mma_gemm
__device__ __nv_bfloat16 g_bpihe [1024*128];
__device__ __nv_bfloat16 g_bwih0e[4096*512];
__device__ __nv_bfloat16 g_bproj1[512*1024];
// states / activations
__device__ __nv_bfloat16 g_bwh1  [32*1024];
__device__ __nv_bfloat16 g_bwh0  [32*1024];
__device__ __nv_bfloat16 g_bph   [2][32*256];
__device__ __nv_bfloat16 g_blastw[32*1024];
__device__ __nv_bfloat16 g_pembin[TT*BATCH*PE];
__device__ __nv_bfloat16 g_wembin[TT*BATCH*WE];
__device__ __nv_bfloat16 g_whseq_bf[(size_t)TT*BATCH*WH];
__device__ __nv_bfloat16 g_wemb_bf[(size_t)WV*WE];
__device__ __nv_bfloat16 g_he_bf[(size_t)TT*BATCH*WE];

#define SMEM_A1  0
#define SMEM_A2  66048
#define SMEM_RED 132096
#define SMEM_DYN 166912

__device__ __forceinline__ float sigf(float x) { return 1.f/(1.f+expf(-x)); }

__device__ __forceinline__ void mma16816(float* c, const unsigned* a, const unsigned* b)
{
    asm volatile("mma.sync.aligned.m16n8k16.row.col.f32.bf16.bf16.f32 "
        "{%0,%1,%2,%3}, {%4,%5,%6,%7}, {%8,%9}, {%0,%1,%2,%3};"
        : "+f"(c[0]), "+f"(c[1]), "+f"(c[2]), "+f"(c[3])
        : "r"(a[0]), "r"(a[1]), "r"(a[2]), "r"(a[3]), "r"(b[0]), "r"(b[1]));
}
__device__ __forceinline__ void ldsm4(unsigned* r, const void* p)
{
    unsigned ad = (unsigned)__cvta_generic_to_shared(p);
    asm volatile("ldmatrix.sync.aligned.m8n8.x4.shared.b16 {%0,%1,%2,%3}, [%4];"
        : "=r"(r[0]), "=r"(r[1]), "=r"(r[2]), "=r"(r[3]) : "r"(ad));
}
__device__ __forceinline__ unsigned ld_acq(const unsigned* p)
{
    unsigned v;
    asm volatile("ld.acquire.gpu.u32 %0, [%1];" : "=r"(v) : "l"(p) : "memory");
    return v;
}
__device__ __forceinline__ void st_rel(unsigned* p, unsigned v)
{
    asm volatile("st.release.gpu.u32 [%0], %1;" :: "l"(p), "r"(v) : "memory");
}

// ---------------- init ----------------
__global__ void init_kernel(const int* __restrict__ pos, const int* __restrict__ word,
                            const float* __restrict__ pos_emb, const float* __restrict__ word_emb,
                            float* __restrict__ S)
{
    int i = blockIdx.x*blockDim.x + threadIdx.x;
    int st = gridDim.x*blockDim.x;
    for (int x = i; x < TT*BATCH*PE; x += st) {
        int tb = x/PE;
        g_pembin[x] = __float2bfloat16(pos_emb[pos[tb]*PE + x - tb*PE]);
    }
    for (int x = i; x < TT*BATCH*WE; x += st) {
        int tb = x/WE;
        g_wembin[x] = __float2bfloat16(word_emb[word[tb]*WE + x - tb*WE]);
    }
    for (int x = i; x < BATCH*PH; x += st) S[OFF_PC + x] = 0.f;
    for (int x = i; x < 2*BATCH*WH; x += st) S[OFF_WC0 + x] = 0.f;
    unsigned* z1 = (unsigned*)g_bwh1; unsigned* z2 = (unsigned*)g_bwh0; unsigned* z3 = (unsigned*)g_bph;
    for (int x = i; x < 16384; x += st) { z1[x] = 0u; z2[x] = 0u; }
    for (int x = i; x < 8192; x += st) z3[x] = 0u;
    if (i < GRID) g_flags[i] = 0u;
    if (i == 0) g_gen = 0u;
}

// ---------------- conversions ----------------
__global__ void conv_bf16(const float* __restrict__ src, __nv_bfloat16* __restrict__ dst, int n4)
{
    int i = blockIdx.x*blockDim.x + threadIdx.x;
    int st = gridDim.x*blockDim.x;
    const float4* s4 = (const float4*)src;
    for (; i < n4; i += st) {
        float4 v = s4[i];
        *(__nv_bfloat162*)(dst + (size_t)i*4)   = __floats2bfloat162_rn(v.x, v.y);
        *(__nv_bfloat162*)(dst + (size_t)i*4+2) = __floats2bfloat162_rn(v.z, v.w);
    }
}
__device__ __forceinline__ void conv_seg(const float* __restrict__ src, __nv_bfloat16* __restrict__ dst,
                                         int rows, int src_ld, int col0, int cols)
{
    int half = cols >> 1;
    long tot = (long)rows*half;
    long idx = (long)blockIdx.x*blockDim.x + threadIdx.x;
    long st  = (long)gridDim.x*blockDim.x;
    for (long i = idx; i < tot; i += st) {
        int r = (int)(i/half), c = (int)(i - (long)r*half)*2;
        float2 v = *(const float2*)&src[(size_t)r*src_ld + col0 + c];
        *(__nv_bfloat162*)&dst[(size_t)r*cols + c] = __floats2bfloat162_rn(v.x, v.y);
    }
}
// pack W[N, col0:col0+K] into fragment order
__device__ __forceinline__ void pack_seg(const float* __restrict__ src, __nv_bfloat16* __restrict__ dst,
                                         int N, int src_ld, int col0, int K)
{
    int NT = N >> 4, KT = K >> 4;
    long tot = (long)NT*KT*32;
    long idx = (long)blockIdx.x*blockDim.x + threadIdx.x;
    long st  = (long)gridDim.x*blockDim.x;
    for (long i = idx; i < tot; i += st) {
        int lane = (int)(i & 31);
        long tk = i >> 5;
        int kt = (int)(tk % KT);
        int nt = (int)(tk / KT);
        int r0 = nt*16 + (lane>>2);
        int c0 = col0 + kt*16 + 2*(lane&3);
        float2 w0 = *(const float2*)&src[(size_t)r0*src_ld + c0];
        float2 w1 = *(const float2*)&src[(size_t)r0*src_ld + c0 + 8];
        float2 w2 = *(const float2*)&src[(size_t)(r0+8)*src_ld + c0];
        float2 w3 = *(const float2*)&src[(size_t)(r0+8)*src_ld + c0 + 8];
        __nv_bfloat162* d = (__nv_bfloat162*)(dst + i*8);
        d[0] = __floats2bfloat162_rn(w0.x, w0.y);
        d[1] = __floats2bfloat162_rn(w1.x, w1.y);
        d[2] = __floats2bfloat162_rn(w2.x, w2.y);
        d[3] = __floats2bfloat162_rn(w3.x, w3.y);
    }
}
__global__ void conv_all(const float* w2p_W, const float* w_Whh1, const float* w_Whh0,
                         const float* p_Wih0, const float* p_Whh0, const float* p2w_W,
                         const float* w_Wih0, const float* w_Wih1, const float* word_proj1_W)
{
    pack_seg(w2p_W,   g_bw2p,   1024, 1024, 0,   1024);
    pack_seg(w_Whh1,  g_bwhh1,  4096, 1024, 0,   1024);
    pack_seg(w_Whh0,  g_bwhh0,  4096, 1024, 0,   1024);
    pack_seg(p_Wih0,  g_bpih,   1024, 1152, 128, 1024);
    pack_seg(p_Whh0,  g_bphh,   1024, 256,  0,   256);
    pack_seg(p2w_W,   g_bp2w,   256,  256,  0,   256);
    pack_seg(w_Wih0,  g_bwih0p, 4096, 768,  512, 256);
    pack_seg(w_Wih1,  g_bwih1,  4096, 1024, 0,   1024);
    conv_seg(p_Wih0,       g_bpihe,  1024, 1152, 0,   128);
    conv_seg(w_Wih0,       g_bwih0e, 4096, 768,  0,   512);
    conv_seg(word_proj1_W, g_bproj1, 512,  1024, 0,   1024);
}

// ---------------- two-hop acquire/release grid barrier ----------------
__device__ __forceinline__ void grid_bar(unsigned epoch)
{
    __syncthreads();
    if (threadIdx.x == 0) st_rel(&g_flags[blockIdx.x], epoch);
    if (blockIdx.x == 0) {
        if (threadIdx.x < GRID)
            while (ld_acq(&g_flags[threadIdx.x]) < epoch) { }
        __syncthreads();
        if (threadIdx.x == 0) st_rel(&g_gen, epoch);
    }
    if (threadIdx.x == 0)
        while (ld_acq(&g_gen) < epoch) { }
    __syncthreads();
}

// ---------------- persist building blocks ----------------
__device__ __forceinline__ void stage_A(const __nv_bfloat16* __restrict__ A, int K, int ald,
                                        __nv_bfloat16* __restrict__ sd)
{
    int Kc = K >> 3;
    for (int i = threadIdx.x; i < 32*Kc; i += TPB) {
        int row = i/Kc, c = i - row*Kc;
        uint4 v = __ldcg((const uint4*)&A[row*K + (c<<3)]);
        *(uint4*)&sd[row*ald + (c<<3)] = v;
    }
}
__device__ __forceinline__ void gen_accum_p(const __nv_bfloat16* __restrict__ sAp, int ald,
    const __nv_bfloat16* __restrict__ Wp, int KT, int nt, int kb, int ke,
    float* acc, int lane)
{
    const __nv_bfloat16* ar = sAp + (lane&15)*ald + 8*(lane>>4);
    const uint4* wp = (const uint4*)Wp + ((size_t)nt*KT)*32 + lane;
    #pragma unroll 4
    for (int kk = kb; kk < ke; kk++) {
        unsigned a0[4], a1[4];
        uint4 w = __ldg(wp + (size_t)kk*32);
        ldsm4(a0, ar + kk*16);
        ldsm4(a1, ar + 16*ald + kk*16);
        unsigned b0[2] = {w.x, w.y}, b1[2] = {w.z, w.w};
        mma16816(acc+0, a0, b0);  mma16816(acc+8, a1, b0);
        mma16816(acc+4, a0, b1);  mma16816(acc+12, a1, b1);
    }
}
__device__ __forceinline__ void red_store(float* red, int wrp, int lane, const float* acc)
{
    float* p = red + (wrp*32 + lane)*17;
    #pragma unroll
    for (int i = 0; i < 16; i++) p[i] = acc[i];
}
__device__ __forceinline__ float red_gather(const float* red, int ts, int li, int ai)
{
    const float* p = red + (ts*4*32 + li)*17 + ai;
    return p[0] + p[32*17] + p[2*32*17] + p[3*32*17];
}
__device__ __forceinline__ void elem_map(int b, int jl, int& li, int& ai)
{
    li = (b&7)*4 + ((jl&7)>>1);
    ai = (b>>4)*8 + (jl>>3)*4 + ((b>>3)&1)*2 + (jl&1);
}

// ---------------- persistent tensor-core sequential phase ----------------
__global__ __launch_bounds__(TPB, 1) void persist_kernel(
    const float* __restrict__ w2p_b, const float* __restrict__ p2w_b,
    const float* __restrict__ w_bih1, const float* __restrict__ w_bhh1,
    float* __restrict__ S)
{
    extern __shared__ char smem[];
    __nv_bfloat16* sA1 = (__nv_bfloat16*)(smem + SMEM_A1);
    __nv_bfloat16* sA2 = (__nv_bfloat16*)(smem + SMEM_A2);
    float* red = (float*)(smem + SMEM_RED);

    float* gpseq = S + OFF_GPSEQ;
    float* gwseq = S + OFF_GWSEQ;
    float* pc    = S + OFF_PC;
    float* wc0   = S + OFF_WC0;
    float* wc1   = S + OFF_WC1;
    float* wg0h  = S + OFF_WG0H;
    float* wg1h  = S + OFF_WG1H;
    float* phseq = S + OFF_PHSEQ;

    int lane = threadIdx.x & 31;
    int wrp  = threadIdx.x >> 5;
    int ts   = wrp >> 2;
    int ks   = wrp & 3;
    int eb   = threadIdx.x >> 4;
    int ej   = threadIdx.x & 15;
    int eli, eai;
    elem_map(eb, ej, eli, eai);
    int pp = 0;
    unsigned epoch = 0;

    for (int t = 0; t < TT; t++) {
        // ===== A: lastw = tanh(wh1 @ w2p^T + b) — 64 tiles / 16 blocks =====
        if (blockIdx.x < 16) {
            stage_A(g_bwh1, 1024, SLDA, sA1);
            __syncthreads();
            int nt = blockIdx.x*4 + ts;
            float acc[16];
            #pragma unroll
            for (int i = 0; i < 16; i++) acc[i] = 0.f;
            gen_accum_p(sA1, SLDA, g_bw2p, 64, nt, ks*16, ks*16+16, acc, lane);
            red_store(red, wrp, lane, acc);
            __syncthreads();
            #pragma unroll
            for (int tt2 = 0; tt2 < 4; tt2++) {
                int n = (blockIdx.x*4 + tt2)*16 + ej;
                float v = red_gather(red, tt2, eli, eai);
                g_blastw[eb*1024 + n] = __float2bfloat16(tanhf(v + w2p_b[n]));
            }
        }
        grid_bar(++epoch);

        // ===== B: POS gates+cell (blocks 0-15) || wg1h/wg0h (blocks 16-143) =====
        if (blockIdx.x < 16) {
            stage_A(g_blastw, 1024, SLDA, sA1);
            stage_A(g_bph[pp], 256, SLDA2, sA2);
            __syncthreads();
            int j0 = blockIdx.x*16;
            int nt = ts*16 + blockIdx.x;
            float acc[16];
            #pragma unroll
            for (int i = 0; i < 16; i++) acc[i] = 0.f;
            int sb = ks*20, se = sb + 20;
            if (sb < 64) gen_accum_p(sA1, SLDA, g_bpih, 64, nt, sb, se < 64 ? se : 64, acc, lane);
            if (se > 64) gen_accum_p(sA2, SLDA2, g_bphh, 16, nt, sb > 64 ? sb-64 : 0, se-64, acc, lane);
            red_store(red, wrp, lane, acc);
            __syncthreads();
            {
                int j = j0 + ej;
                const float* pre = gpseq + ((size_t)t*BATCH + eb)*(4*PH) + j;
                float gi = red_gather(red, 0, eli, eai) + pre[0*PH];
                float gf = red_gather(red, 1, eli, eai) + pre[1*PH];
                float gg = red_gather(red, 2, eli, eai) + pre[2*PH];
                float go = red_gather(red, 3, eli, eai) + pre[3*PH];
                int idx = eb*PH + j;
                float cn = sigf(gf)*pc[idx] + sigf(gi)*tanhf(gg);
                float hn = sigf(go)*tanhf(cn);
                pc[idx] = cn;
                g_bph[pp^1][idx] = __float2bfloat16(hn);
                phseq[((size_t)t*BATCH + eb)*PH + j] = hn;
            }
        } else {
            int base = (blockIdx.x - 16)*4;
            if (base < 512) {
                const __nv_bfloat16* sAu;
                if (base < 256) { stage_A(g_bwh1, 1024, SLDA, sA1); sAu = sA1; }
                else            { stage_A(g_bwh0, 1024, SLDA, sA2); sAu = sA2; }
                __syncthreads();
                int wt = base + ts;
                const __nv_bfloat16* Wp = (wt < 256) ? g_bwhh1 : g_bwhh0;
                int nt = (wt < 256) ? wt : wt - 256;
                float acc[16];
                #pragma unroll
                for (int i = 0; i < 16; i++) acc[i] = 0.f;
                gen_accum_p(sAu, SLDA, Wp, 64, nt, ks*16, ks*16+16, acc, lane);
                red_store(red, wrp, lane, acc);
                __syncthreads();
                #pragma unroll
                for (int tt2 = 0; tt2 < 4; tt2++) {
                    int wt2 = base + tt2;
                    float v = red_gather(red, tt2, eli, eai);
                    if (wt2 < 256) wg1h[eb*4096 + wt2*16 + ej] = v;
                    else           wg0h[eb*4096 + (wt2-256)*16 + ej] = v;
                }
            }
        }
        grid_bar(++epoch);

        // ===== S4: lastp prologue + WORD L0 gates + cell — 64 blocks =====
        if (blockIdx.x < 64) {
            stage_A(g_bph[pp^1], 256, SLDA2, sA2);
            __syncthreads();
            {
                float pacc[16];
                #pragma unroll
                for (int i = 0; i < 16; i++) pacc[i] = 0.f;
                gen_accum_p(sA2, SLDA2, g_bp2w, 16, wrp, 0, 16, pacc, lane);
                int n0 = wrp*16;
                #pragma unroll
                for (int mf = 0; mf < 2; mf++)
                #pragma unroll
                for (int f = 0; f < 2; f++) {
                    int rb = mf*16 + (lane>>2);
                    int cl = n0 + f*8 + 2*(lane&3);
                    float b0 = p2w_b[cl], b1 = p2w_b[cl+1];
                    const float* a = pacc + mf*8 + f*4;
                    *(__nv_bfloat162*)&sA1[rb*SLDA + cl] =
                        __floats2bfloat162_rn(tanhf(a[0]+b0), tanhf(a[1]+b1));
                    *(__nv_bfloat162*)&sA1[(rb+8)*SLDA + cl] =
                        __floats2bfloat162_rn(tanhf(a[2]+b0), tanhf(a[3]+b1));
                }
            }
            __syncthreads();
            int j0 = blockIdx.x*16;
            int nt = ts*64 + blockIdx.x;
            float acc[16];
            #pragma unroll
            for (int i = 0; i < 16; i++) acc[i] = 0.f;
            gen_accum_p(sA1, SLDA, g_bwih0p, 16, nt, ks*4, ks*4+4, acc, lane);
            red_store(red, wrp, lane, acc);
            __syncthreads();
            {
                int j = j0 + ej;
                const float* pre = gwseq + ((size_t)t*BATCH + eb)*(4*WH) + j;
                const float* hid = wg0h + (size_t)eb*4096 + j;
                float gi = red_gather(red, 0, eli, eai) + pre[0*WH] + __ldcg(hid + 0*WH);
                float gf = red_gather(red, 1, eli, eai) + pre[1*WH] + __ldcg(hid + 1*WH);
                float gg = red_gather(red, 2, eli, eai) + pre[2*WH] + __ldcg(hid + 2*WH);
                float go = red_gather(red, 3, eli, eai) + pre[3*WH] + __ldcg(hid + 3*WH);
                int idx = eb*WH + j;
                float cn = sigf(gf)*wc0[idx] + sigf(gi)*tanhf(gg);
                float hn = sigf(go)*tanhf(cn);
                wc0[idx] = cn;
                g_bwh0[idx] = __float2bfloat16(hn);
            }
        }
        grid_bar(++epoch);

        // ===== S5: WORD L1 gates + cell — 64 blocks, K=1024 =====
        if (blockIdx.x < 64) {
            stage_A(g_bwh0, 1024, SLDA, sA1);
            __syncthreads();
            int j0 = blockIdx.x*16;
            int nt = ts*64 + blockIdx.x;
            float acc[16];
            #pragma unroll
            for (int i = 0; i < 16; i++) acc[i] = 0.f;
            gen_accum_p(sA1, SLDA, g_bwih1, 64, nt, ks*16, ks*16+16, acc, lane);
            red_store(red, wrp, lane, acc);
            __syncthreads();
            {
                int j = j0 + ej;
                const float* hid = wg1h + (size_t)eb*4096 + j;
                float gi = red_gather(red, 0, eli, eai) + __ldcg(hid + 0*WH) + w_bih1[0*WH+j] + w_bhh1[0*WH+j];
                float gf = red_gather(red, 1, eli, eai) + __ldcg(hid + 1*WH) + w_bih1[1*WH+j] + w_bhh1[1*WH+j];
                float gg = red_gather(red, 2, eli, eai) + __ldcg(hid + 2*WH) + w_bih1[2*WH+j] + w_bhh1[2*WH+j];
                float go = red_gather(red, 3, eli, eai) + __ldcg(hid + 3*WH) + w_bih1[3*WH+j] + w_bhh1[3*WH+j];
                int idx = eb*WH + j;
                float cn = sigf(gf)*wc1[idx] + sigf(gi)*tanhf(gg);
                float hn = sigf(go)*tanhf(cn);
                wc1[idx] = cn;
                g_bwh1[idx] = __float2bfloat16(hn);
                g_whseq_bf[((size_t)t*BATCH + eb)*WH + j] = __float2bfloat16(hn);
            }
        }
        grid_bar(++epoch);
        pp ^= 1;
    }
}

// ---------------- generic bf16 mma GEMM ----------------
template<int OUT_BF>
__global__ __launch_bounds__(256) void mma_gemm(const __nv_bfloat16* __restrict__ Abf,
                                                const __nv_bfloat16* __restrict__ Bbf,
                                                const float* __restrict__ bias1,
                                                const float* __restrict__ bias2,
                                                void* __restrict__ Cv, int N, int K)
{
    __shared__ __nv_bfloat16 sAm[128][40];
    __shared__ __nv_bfloat16 sBm[128][40];
    int tid = threadIdx.x, lane = tid&31, wid = tid>>5;
    int wm = wid>>2, wn = wid&3;
    int bm = blockIdx.y*128, bn = blockIdx.x*128;
    float acc[4][4][4] = {};
    for (int kt = 0; kt < K; kt += 32) {
        __syncthreads();
        #pragma unroll
        for (int c = 0; c < 2; c++) {
            int ch = tid + c*256;
            int row = ch>>2, seg = (ch&3)*8;
            *(uint4*)&sAm[row][seg] = *(const uint4*)&Abf[(size_t)(bm+row)*K + kt + seg];
            *(uint4*)&sBm[row][seg] = *(const uint4*)&Bbf[(size_t)(bn+row)*K + kt + seg];
        }
        __syncthreads();
        #pragma unroll
        for (int k16 = 0; k16 < 2; k16++) {
            unsigned afrag[4][4], bfrag[4][2];
            #pragma unroll
            for (int mf = 0; mf < 4; mf++)
                ldsm4(afrag[mf], &sAm[wm*64 + mf*16 + (lane&15)][k16*16 + (lane>>4)*8]);
            #pragma unroll
            for (int np = 0; np < 2; np++) {
                unsigned r[4];
                ldsm4(r, &sBm[wn*32 + np*16 + (lane&7) + ((lane>>4)<<3)][k16*16 + (((lane>>3)&1)<<3)]);
                bfrag[np*2][0] = r[0]; bfrag[np*2][1] = r[1];
                bfrag[np*2+1][0] = r[2]; bfrag[np*2+1][1] = r[3];
            }
            #pragma unroll
            for (int mf = 0; mf < 4; mf++)
                #pragma unroll
                for (int nf = 0; nf < 4; nf++)
                    mma16816(acc[mf][nf], afrag[mf], bfrag[nf]);
        }
    }
    int tg = lane>>2, tc = (lane&3)*2;
    #pragma unroll
    for (int nf = 0; nf < 4; nf++) {
        int n = bn + wn*32 + nf*8 + tc;
        float b0 = (bias1 ? bias1[n]   : 0.f) + (bias2 ? bias2[n]   : 0.f);
        float b1 = (bias1 ? bias1[n+1] : 0.f) + (bias2 ? bias2[n+1] : 0.f);
        #pragma unroll
        for (int mf = 0; mf < 4; mf++) {
            int m0 = bm + wm*64 + mf*16 + tg;
            float v00 = acc[mf][nf][0]+b0, v01 = acc[mf][nf][1]+b1;
            float v10 = acc[mf][nf][2]+b0, v11 = acc[mf][nf][3]+b1;
            if (OUT_BF) {
                __nv_bfloat16* C = (__nv_bfloat16*)Cv;
                *(__nv_bfloat162*)&C[(size_t)m0*N + n]     = __floats2bfloat162_rn(v00, v01);
                *(__nv_bfloat162*)&C[(size_t)(m0+8)*N + n] = __floats2bfloat162_rn(v10, v11);
            } else {
                float* C = (float*)Cv;
                *(float2*)&C[(size_t)m0*N + n]     = make_float2(v00, v01);
                *(float2*)&C[(size_t)(m0+8)*N + n] = make_float2(v10, v11);
            }
        }
    }
}

// ---------------- pos projection + log_softmax ----------------
__global__ void pos_out_kernel(const float* __restrict__ phseq, const float* __restrict__ proj_W,
                               const float* __restrict__ proj_b, float* __restrict__ out)
{
    int row = blockIdx.x;
    const float* h = phseq + row*PH;
    __shared__ float sh[PH];
    __shared__ float logits[PV];
    __shared__ float lse;
    for (int i = threadIdx.x; i < PH; i += 64) sh[i] = h[i];
    __syncthreads();
    if (threadIdx.x < PV) {
        float s = proj_b[threadIdx.x];
        const float* wr = proj_W + threadIdx.x*PH;
        #pragma unroll 4
        for (int k = 0; k < PH; k++) s += sh[k]*wr[k];
        logits[threadIdx.x] = s;
    }
    __syncthreads();
    if (threadIdx.x == 0) {
        float m = -1e30f;
        for (int i = 0; i < PV; i++) m = fmaxf(m, logits[i]);
        float ssum = 0.f;
        for (int i = 0; i < PV; i++) ssum += expf(logits[i]-m);
        lse = m + logf(ssum);
    }
    __syncthreads();
    if (threadIdx.x < PV) out[row*PV + threadIdx.x] = logits[threadIdx.x] - lse;
}

// ---------------- in-place log_softmax (word) ----------------
__global__ void word_lsm(float* __restrict__ out)
{
    int row = blockIdx.x;
    float* r = out + (long)row*WV;
    float m = -1e30f, s = 0.f;
    for (int i = threadIdx.x; i < WV; i += blockDim.x) {
        float v = r[i];
        if (v > m) { s = s*expf(m-v) + 1.f; m = v; } else s += expf(v-m);
    }
    __shared__ float sm[256], ss[256];
    sm[threadIdx.x] = m; ss[threadIdx.x] = s;
    __syncthreads();
    for (int off = 128; off > 0; off >>= 1) {
        if (threadIdx.x < off) {
            float m1 = sm[threadIdx.x], s1 = ss[threadIdx.x];
            float m2 = sm[threadIdx.x+off], s2 = ss[threadIdx.x+off];
            float mm = fmaxf(m1, m2);
            sm[threadIdx.x] = mm;
            ss[threadIdx.x] = s1*expf(m1-mm) + s2*expf(m2-mm);
        }
        __syncthreads();
    }
    float lse = sm[0] + logf(ss[0]);
    for (int i = threadIdx.x; i < WV; i += blockDim.x) r[i] -= lse;
}

// ---------------- host ----------------
extern "C" void kernel_launch(void* const* d_in, const int* in_sizes, int n_in,
                              void* d_out, int out_size)
{
    (void)in_sizes; (void)n_in; (void)out_size;
    const int*   pos          = (const int*)  d_in[0];
    const int*   word         = (const int*)  d_in[1];
    const float* pos_emb_W    = (const float*)d_in[2];
    const float* word_emb_W   = (const float*)d_in[3];
    const float* w2p_W        = (const float*)d_in[4];
    const float* w2p_b        = (const float*)d_in[5];
    const float* p2w_W        = (const float*)d_in[6];
    const float* p2w_b        = (const float*)d_in[7];
    const float* p_Wih0       = (const float*)d_in[8];
    const float* p_Whh0       = (const float*)d_in[9];
    const float* p_bih0       = (const float*)d_in[10];
    const float* p_bhh0       = (const float*)d_in[11];
    const float* w_Wih0       = (const float*)d_in[12];
    const float* w_Whh0       = (const float*)d_in[13];
    const float* w_bih0       = (const float*)d_in[14];
    const float* w_bhh0       = (const float*)d_in[15];
    const float* w_Wih1       = (const float*)d_in[16];
    const float* w_Whh1       = (const float*)d_in[17];
    const float* w_bih1       = (const float*)d_in[18];
    const float* w_bhh1       = (const float*)d_in[19];
    const float* pos_proj_W   = (const float*)d_in[20];
    const float* pos_proj_b   = (const float*)d_in[21];
    const float* word_proj1_W = (const float*)d_in[22];
    const float* word_proj1_b = (const float*)d_in[23];
    const float* word_proj2_b = (const float*)d_in[24];
    float* out = (float*)d_out;

    float* S; cudaGetSymbolAddress((void**)&S, g_scratch);
    __nv_bfloat16 *wemb_bf, *he_bf, *pembin, *wembin, *whseq_bf, *bpihe, *bwih0e, *bproj1;
    cudaGetSymbolAddress((void**)&wemb_bf, g_wemb_bf);
    cudaGetSymbolAddress((void**)&he_bf, g_he_bf);
    cudaGetSymbolAddress((void**)&pembin, g_pembin);
    cudaGetSymbolAddress((void**)&wembin, g_wembin);
    cudaGetSymbolAddress((void**)&whseq_bf, g_whseq_bf);
    cudaGetSymbolAddress((void**)&bpihe, g_bpihe);
    cudaGetSymbolAddress((void**)&bwih0e, g_bwih0e);
    cudaGetSymbolAddress((void**)&bproj1, g_bproj1);

    float* gpseq = S + OFF_GPSEQ;
    float* gwseq = S + OFF_GWSEQ;
    float* phseq = S + OFF_PHSEQ;

    static bool attr_set = false;
    if (!attr_set) {
        cudaFuncSetAttribute(persist_kernel, cudaFuncAttributeMaxDynamicSharedMemorySize, SMEM_DYN);
        attr_set = true;
    }

    init_kernel<<<512, 256>>>(pos, word, pos_emb_W, word_emb_W, S);
    conv_bf16<<<2048, 256>>>(word_emb_W, wemb_bf, (int)((size_t)WV*WE/4));
    conv_all<<<592, 256>>>(w2p_W, w_Whh1, w_Whh0, p_Wih0, p_Whh0, p2w_W,
                           w_Wih0, w_Wih1, word_proj1_W);

    mma_gemm<0><<<dim3(4*PH/128, TT*BATCH/128), 256>>>(pembin, bpihe, p_bih0, p_bhh0,
                                                       gpseq, 4*PH, PE);
    mma_gemm<0><<<dim3(4*WH/128, TT*BATCH/128), 256>>>(wembin, bwih0e, w_bih0, w_bhh0,
                                                       gwseq, 4*WH, WE);

    persist_kernel<<<GRID, TPB, SMEM_DYN>>>(w2p_b, p2w_b, w_bih1, w_bhh1, S);

    pos_out_kernel<<<TT*BATCH, 64>>>(phseq, pos_proj_W, pos_proj_b, out);

    mma_gemm<1><<<dim3(WE/128, TT*BATCH/128), 256>>>(whseq_bf, bproj1, word_proj1_b, nullptr,
                                                     he_bf, WE, WH);
    float* wout = out + (long)TT*BATCH*PV;
    mma_gemm<0><<<dim3(WV/128, TT*BATCH/128), 256>>>(he_bf, wemb_bf, word_proj2_b, nullptr,
                                                     wout, WV, WE);
    word_lsm<<<TT*BATCH, 256>>>(wout);
}